// round 10
// baseline (speedup 1.0000x reference)
#include <cuda_runtime.h>
#include <cstdint>

// CRF forward (linear-chain log-partition), B=64, T=2048, K=256.
// 1 cluster (2 CTAs) per batch row, 512 threads/CTA. Column-split in exp-domain:
// CTA r holds E[j, i] for ALL 256 j over its own 128 i-columns; each j's half-dot
// is split across 2 threads (64 cols each, 32 f32x2 FMAs). Scores kept as
// P = exp(s - c): tail is P' = yexp * v * rv (no transcendentals on the path).
// Partials exchanged via st.async into one tx-mbarrier (peer subs + own upper
// subs, 3072 B). Running shift c and rv = 1/v* maintained by thread JSTAR
// off-path. Masked suffix skipped (len = sum mask). No __syncthreads in loop.

#define KSZ 256
#define TSZ 2048
#define SOSI 2
#define JSTAR 16

__device__ __forceinline__ float ex2f(float x) {
    float r; asm("ex2.approx.ftz.f32 %0, %1;" : "=f"(r) : "f"(x)); return r;
}
__device__ __forceinline__ float lg2f_(float x) {
    float r; asm("lg2.approx.ftz.f32 %0, %1;" : "=f"(r) : "f"(x)); return r;
}
__device__ __forceinline__ float rcpf_(float x) {
    float r; asm("rcp.approx.ftz.f32 %0, %1;" : "=f"(r) : "f"(x)); return r;
}
__device__ __forceinline__ void unpack2(unsigned long long v, float& lo, float& hi) {
    asm("mov.b64 {%0, %1}, %2;" : "=f"(lo), "=f"(hi) : "l"(v));
}
__device__ __forceinline__ unsigned long long pack2(float lo, float hi) {
    unsigned long long r; asm("mov.b64 %0, {%1, %2};" : "=l"(r) : "f"(lo), "f"(hi)); return r;
}
__device__ __forceinline__ void fma2(unsigned long long& d, unsigned long long a, unsigned long long b) {
    asm("fma.rn.f32x2 %0, %1, %2, %0;" : "+l"(d) : "l"(a), "l"(b));
}
__device__ __forceinline__ uint32_t smem_u32(const void* p) {
    uint32_t a;
    asm("{ .reg .u64 t; cvta.to.shared.u64 t, %1; cvt.u32.u64 %0, t; }" : "=r"(a) : "l"(p));
    return a;
}
__device__ __forceinline__ uint32_t mapa_u32(uint32_t a, uint32_t rk) {
    uint32_t r; asm("mapa.shared::cluster.u32 %0, %1, %2;" : "=r"(r) : "r"(a), "r"(rk)); return r;
}
__device__ __forceinline__ void st_async_b32(uint32_t dst_addr, float v, uint32_t dst_bar) {
    asm volatile("st.async.shared::cluster.mbarrier::complete_tx::bytes.b32 [%0], %1, [%2];"
                 :: "r"(dst_addr), "r"(__float_as_uint(v)), "r"(dst_bar) : "memory");
}
__device__ __forceinline__ void mbar_init(uint32_t bar, uint32_t cnt) {
    asm volatile("mbarrier.init.shared.b64 [%0], %1;" :: "r"(bar), "r"(cnt) : "memory");
}
__device__ __forceinline__ void mbar_expect_tx(uint32_t bar, uint32_t bytes) {
    asm volatile("mbarrier.arrive.expect_tx.shared.b64 _, [%0], %1;" :: "r"(bar), "r"(bytes) : "memory");
}
__device__ __forceinline__ void mbar_arrive(uint32_t bar) {
    asm volatile("mbarrier.arrive.shared.b64 _, [%0];" :: "r"(bar) : "memory");
}
__device__ __forceinline__ void mbar_wait_parity(uint32_t bar, uint32_t par) {
    asm volatile(
        "{\n\t.reg .pred P;\n\t"
        "WL_%=:\n\t"
        "mbarrier.try_wait.parity.acquire.cta.shared::cta.b64 P, [%0], %1, 0x989680;\n\t"
        "@P bra.uni WD_%=;\n\t"
        "bra.uni WL_%=;\n\t"
        "WD_%=:\n\t}"
        :: "r"(bar), "r"(par) : "memory");
}
__device__ __forceinline__ void cluster_barrier() {
    asm volatile("barrier.cluster.arrive.aligned;" ::: "memory");
    asm volatile("barrier.cluster.wait.aligned;"   ::: "memory");
}

__global__ void __cluster_dims__(2, 1, 1) __launch_bounds__(512, 1)
crf_fwd_kernel(const float* __restrict__ y,
               const float* __restrict__ mask,
               const float* __restrict__ trans,
               float* __restrict__ out)
{
    constexpr float INV_LN2 = 1.4426950408889634f;
    constexpr float LN2F    = 0.6931471805599453f;

    __shared__ __align__(16) float p_s[2][128];   // local-half P, double-buffered
    __shared__ float rsub_s[2][768];              // [buf][slot*256+j]: 0=peer-lo,1=peer-hi,2=own-hi
    __shared__ float rv_s[2];                     // lagged 1/v*
    __shared__ float c_s;                         // final shift
    __shared__ float sfin_s[KSZ];                 // final P
    __shared__ float lred_s[16];
    __shared__ int   len_s;
    __shared__ __align__(8) unsigned long long mbarP[2];  // partials delivered (tx)
    __shared__ __align__(8) unsigned long long mbarPP[2]; // P published (count=8)

    const int tid   = threadIdx.x;
    const int w     = tid >> 5;
    const int lane  = tid & 31;
    const int j     = tid & 255;          // row this thread contributes to
    const int half  = tid >> 8;           // 0: i-sub [0,64), 1: i-sub [64,128) of local cols
    const bool lower = (half == 0);

    uint32_t rank; asm("mov.u32 %0, %%cluster_ctarank;" : "=r"(rank));
    const uint32_t peer = rank ^ 1u;
    const int b = blockIdx.x >> 1;

    // ---------------- setup ----------------
    if (tid == 0) {
        mbar_init(smem_u32(&mbarP[0]), 1);
        mbar_init(smem_u32(&mbarP[1]), 1);
        mbar_init(smem_u32(&mbarPP[0]), 8);       // 8 lower warps arrive
        mbar_init(smem_u32(&mbarPP[1]), 8);
        rv_s[0] = 1.0f;
        c_s = 0.0f;
    }
    // len = sum(mask row b)
    {
        float ms = 0.0f;
        for (int i = tid; i < TSZ; i += 512) ms += mask[(size_t)b * TSZ + i];
        #pragma unroll
        for (int o = 16; o; o >>= 1) ms += __shfl_xor_sync(0xffffffffu, ms, o);
        if (lane == 0) lred_s[w] = ms;
    }
    if (tid < 128) p_s[0][tid] = (rank == 0 && tid == SOSI) ? 1.0f : 0.0f;
    __syncthreads();
    if (tid == 0) {
        float s = 0.0f;
        #pragma unroll
        for (int k = 0; k < 16; k++) s += lred_s[k];
        len_s = (int)(s + 0.5f);
    }

    // Full-row max (identical on both CTAs).
    float Mj;
    {
        const float* row = trans + (size_t)j * KSZ;
        float mx = row[0];
        #pragma unroll 8
        for (int i = 1; i < KSZ; i++) mx = fmaxf(mx, row[i]);
        Mj = mx;
    }
    // Register-resident E: 64 columns starting at rank*128 + half*64.
    unsigned long long E2[32];
    {
        const float* row = trans + (size_t)j * KSZ + (int)rank * 128 + half * 64;
        #pragma unroll 8
        for (int k = 0; k < 32; k++) {
            float e0 = ex2f((row[2 * k]     - Mj) * INV_LN2);
            float e1 = ex2f((row[2 * k + 1] - Mj) * INV_LN2);
            E2[k] = pack2(e0, e1);
        }
    }

    // Destination addresses for the partial sends.
    const uint32_t pa_r0 = mapa_u32(smem_u32(&rsub_s[0][half * 256 + j]), peer);
    const uint32_t pa_r1 = mapa_u32(smem_u32(&rsub_s[1][half * 256 + j]), peer);
    const uint32_t pa_b0 = mapa_u32(smem_u32(&mbarP[0]), peer);
    const uint32_t pa_b1 = mapa_u32(smem_u32(&mbarP[1]), peer);
    uint32_t la_r0 = 0, la_r1 = 0, la_b0 = 0, la_b1 = 0;
    if (!lower) {   // upper half also feeds its own CTA's tail via local st.async
        la_r0 = mapa_u32(smem_u32(&rsub_s[0][512 + j]), rank);
        la_r1 = mapa_u32(smem_u32(&rsub_s[1][512 + j]), rank);
        la_b0 = mapa_u32(smem_u32(&mbarP[0]), rank);
        la_b1 = mapa_u32(smem_u32(&mbarP[1]), rank);
    }

    // y pipeline (lower threads only): yexp = exp(y + Mj), 2 steps deep.
    const float* ybase = y + (size_t)b * TSZ * KSZ + j;
    float yx_n = 0.0f, y_r = 0.0f, pv = 0.0f, c_run = 0.0f, vstar = 1.0f;
    if (lower) {
        yx_n = ex2f((__ldg(ybase) + Mj) * INV_LN2);
        y_r  = __ldg(ybase + KSZ);
    }
    const bool own  = ((j >> 7) == (int)rank);     // this j's P is published locally
    const int  il   = j & 127;

    __syncthreads();
    cluster_barrier();    // barriers + p0 + rv visible cluster-wide
    const int len = len_s;

    // ---------------- sequential scan ----------------
    for (int t = 0; t < len; t++) {
        const int pb = t & 1, nb = pb ^ 1;

        if (tid == 0) mbar_expect_tx(smem_u32(&mbarP[pb]), 3072);

        float yx_c = yx_n;
        if (lower) {
            yx_n = ex2f((y_r + Mj) * INV_LN2);
            if (t + 2 < TSZ) y_r = __ldg(ybase + (size_t)(t + 2) * KSZ);
        }

        if (t > 0) mbar_wait_parity(smem_u32(&mbarPP[pb]), ((unsigned)(t - 1) >> 1) & 1u);
        const float rv = rv_s[pb];

        // 64-column sub dot-product: 32 packed FMAs, 4 accumulators.
        unsigned long long a0 = 0ull, a1 = 0ull, a2 = 0ull, a3 = 0ull;
        const ulonglong2* pp = reinterpret_cast<const ulonglong2*>(p_s[pb] + half * 64);
        #pragma unroll
        for (int q = 0; q < 8; q++) {
            ulonglong2 v1 = pp[2 * q];
            ulonglong2 v2 = pp[2 * q + 1];
            fma2(a0, E2[4 * q],     v1.x);
            fma2(a1, E2[4 * q + 1], v1.y);
            fma2(a2, E2[4 * q + 2], v2.x);
            fma2(a3, E2[4 * q + 3], v2.y);
        }
        float x0, x1, x2, x3, x4, x5, x6, x7;
        unpack2(a0, x0, x1); unpack2(a1, x2, x3);
        unpack2(a2, x4, x5); unpack2(a3, x6, x7);
        const float P = ((x0 + x2) + (x1 + x3)) + ((x4 + x6) + (x5 + x7));

        // Ship the sub-partial: to the peer always; upper half also to own CTA.
        st_async_b32(pb ? pa_r1 : pa_r0, P, pb ? pa_b1 : pa_b0);
        if (!lower) {
            st_async_b32(pb ? la_r1 : la_r0, P, pb ? la_b1 : la_b0);
        } else {
            // Tail: wait all 4 sub-partials (peer x2 + own upper), finish in exp-domain.
            mbar_wait_parity(smem_u32(&mbarP[pb]), ((unsigned)t >> 1) & 1u);
            const float v = ((P + rsub_s[pb][512 + j]) +
                             (rsub_s[pb][j] + rsub_s[pb][256 + j]));
            const float pn = yx_c * v * rv;          // P_{t+1}[j]
            pv = pn;
            if (own) p_s[nb][il] = pn;
            if (j == JSTAR) {
                c_run += lg2f_(vstar) * LN2F;        // c += ln v*_{t-1}
                vstar  = v;
                rv_s[nb] = rcpf_(v);                 // 1/v*_t for step t+1
            }
            __syncwarp();
            if (lane == 0) mbar_arrive(smem_u32(&mbarPP[nb]));
        }
    }

    // ---------------- final: out = c + ln(sum_j P) ----------------
    if (lower) {
        sfin_s[j] = pv;
        if (j == JSTAR) c_s = c_run;
    }
    __syncthreads();
    if (rank == 0 && tid < 32) {
        float sum = 0.0f;
        #pragma unroll
        for (int k = 0; k < 8; k++) sum += sfin_s[tid + 32 * k];
        #pragma unroll
        for (int o = 16; o; o >>= 1) sum += __shfl_xor_sync(0xffffffffu, sum, o);
        if (tid == 0) out[b] = c_s + lg2f_(sum) * LN2F;
    }
    cluster_barrier();   // don't exit while peer st.asyncs may be in flight
}

extern "C" void kernel_launch(void* const* d_in, const int* in_sizes, int n_in,
                              void* d_out, int out_size)
{
    const float* y     = (const float*)d_in[0];   // (B, T, K) f32
    const float* mask  = (const float*)d_in[1];   // (B, T)    f32
    const float* trans = (const float*)d_in[2];   // (K, K)    f32
    float* out = (float*)d_out;                   // (B,)      f32

    const int B = in_sizes[1] / TSZ;              // 64
    crf_fwd_kernel<<<2 * B, 512>>>(y, mask, trans, out);
}